// round 4
// baseline (speedup 1.0000x reference)
#include <cuda_runtime.h>

#define EPS 1e-8f
#define BN 4
#define CN 128
#define HN 256
#define WN 256
#define HW (HN*WN)       // 65536
#define NCH (BN*CN)      // 512
#define MHW (128*128)    // 16384
#define NPART 4

// Scratch: per-channel partial sums (NPART parts) + final coefficients.
__device__ float g_sums[NPART * NCH * 12];
__device__ float g_coef[NCH * 4];          // per channel: P, Q, k1, k2
__device__ unsigned int g_cnt[BN];         // zero-init; self-resetting each run

__device__ __forceinline__ float warpSum(float v) {
#pragma unroll
    for (int o = 16; o; o >>= 1) v += __shfl_xor_sync(0xffffffffu, v, o);
    return v;
}

// ---------------------------------------------------------------------------
// Kernel 1: per-(b,c) partial reductions over a quarter of HW, then the LAST
// finishing block of each batch computes the batch's final coefficients
// (mask sums, combine partials, per-channel stats, 4 modulation GEMVs).
//   var identity: Sum((x - mu)*m)^2 = C - 2*mu*B + mu^2*Sum(m^2)
//   with A = Sum x*m, B = Sum x*m^3, C = Sum x^2*m^4
//   final: out = x1*(m^2*P + om^2*Q) + k1*m + k2*om
// x1 loaded with default policy (keep L2-resident for k_apply's re-read);
// x2 streamed with __ldcs (read exactly once in the whole problem).
// ---------------------------------------------------------------------------
__global__ __launch_bounds__(256, 6) void k_reduce(const float4* __restrict__ x1,
                                                   const float4* __restrict__ x2,
                                                   const float* __restrict__ mask,
                                                   const float* __restrict__ w_in_mean,
                                                   const float* __restrict__ w_in_var,
                                                   const float* __restrict__ w_out_mean,
                                                   const float* __restrict__ w_out_var) {
    int ch   = blockIdx.x & (NCH - 1);
    int part = blockIdx.x >> 9;
    int b  = ch >> 7;
    const float4* p1 = x1 + (size_t)ch * (HW / 4) + part * 4096;
    const float4* p2 = x2 + (size_t)ch * (HW / 4) + part * 4096;
    const float*  mb = mask + b * MHW;
    int t = threadIdx.x;
    int lane = t & 31, wid = t >> 5;
    int qbase = part * 4096;

    float acc[12];
#pragma unroll
    for (int i = 0; i < 12; i++) acc[i] = 0.f;

#pragma unroll 1
    for (int k = 0; k < 16; k += 2) {
        int qa = t + k * 256;
        int qb = qa + 256;
        float4 v1a = p1[qa];
        float4 v2a = __ldcs(p2 + qa);
        float4 v1b = p1[qb];
        float4 v2b = __ldcs(p2 + qb);
        int qga = qbase + qa, qgb = qbase + qb;
        int ma_i = ((qga >> 7) << 7) | ((2 * qga) & 126);
        int mb_i = ((qgb >> 7) << 7) | ((2 * qgb) & 126);
        float2 mpa = *reinterpret_cast<const float2*>(mb + ma_i);
        float2 mpb = *reinterpret_cast<const float2*>(mb + mb_i);

#pragma unroll
        for (int half = 0; half < 2; half++) {
            float4 v1 = half ? v1b : v1a;
            float4 v2 = half ? v2b : v2a;
            float2 mp = half ? mpb : mpa;
            float mv[4]  = {mp.x, mp.x, mp.y, mp.y};
            float xv1[4] = {v1.x, v1.y, v1.z, v1.w};
            float xv2[4] = {v2.x, v2.y, v2.z, v2.w};
#pragma unroll
            for (int i = 0; i < 4; i++) {
                float m = mv[i], om = 1.0f - m;
                float mm = m * m, omm = om * om;
                float x = xv1[i];
                acc[0] += x * m;   float tt = x * mm;  acc[1] += tt * m;  acc[2] += tt * tt;
                acc[3] += x * om;  float t2 = x * omm; acc[4] += t2 * om; acc[5] += t2 * t2;
                x = xv2[i];
                acc[6] += x * m;   tt = x * mm;        acc[7] += tt * m;  acc[8] += tt * tt;
                acc[9] += x * om;  t2 = x * omm;       acc[10] += t2 * om; acc[11] += t2 * t2;
            }
        }
    }

    __shared__ float red[12][8];
#pragma unroll
    for (int i = 0; i < 12; i++) {
        float s = warpSum(acc[i]);
        if (lane == 0) red[i][wid] = s;
    }
    __syncthreads();
    if (wid == 0) {
#pragma unroll
        for (int i = 0; i < 12; i++) {
            float s = (lane < 8) ? red[i][lane] : 0.f;
            s = warpSum(s);
            if (lane == 0) g_sums[(size_t)(part * NCH + ch) * 12 + i] = s;
        }
    }

    // ---- last-block-finishes: per-batch final phase --------------------
    __shared__ unsigned int isLast;
    __threadfence();
    __syncthreads();
    if (t == 0) {
        unsigned int v = atomicAdd(&g_cnt[b], 1u);
        isLast = (v == (unsigned)(NPART * CN - 1)) ? 1u : 0u;
    }
    __syncthreads();
    if (!isLast) return;
    __threadfence();                    // acquire: see all g_sums writes

    __shared__ float sred[2][8];
    __shared__ float ssum[CN * 12];
    __shared__ float v_sh[4 * 256];     // GEMV input vectors per matrix
    __shared__ float mr_sh[512];        // mu_in, r_in, mu_out, r_out
    __shared__ float ada_sh[512];       // [mat*128 + c]
    __shared__ float sh_nin, sh_nout, sh_M2, sh_M2o;

    // mask sums (exact: 2x2 repeat upsample => Sum m = 4*Sum mask, etc.)
    {
        float s1 = 0, s2 = 0;
        for (int i = t; i < MHW; i += 256) { float m = mb[i]; s1 += m; s2 += m * m; }
        s1 = warpSum(s1); s2 = warpSum(s2);
        if (lane == 0) { sred[0][wid] = s1; sred[1][wid] = s2; }
    }

    // combine the NPART partial sums
    for (int id = t; id < CN * 12; id += 256) {
        int c = id / 12, i = id - c * 12;
        float v = 0.f;
#pragma unroll
        for (int p = 0; p < NPART; p++)
            v += g_sums[(size_t)(p * NCH + b * CN + c) * 12 + i];
        ssum[id] = v;
    }
    __syncthreads();

    if (t == 0) {
        float S1 = 0, S2 = 0;
        for (int i = 0; i < 8; i++) { S1 += sred[0][i]; S2 += sred[1][i]; }
        float msum = 4.f * S1, m2sum = 4.f * S2;
        sh_nin  = msum + EPS;
        sh_nout = ((float)HW - msum) + EPS;
        sh_M2   = m2sum;
        sh_M2o  = (float)HW - 2.f * msum + m2sum;   // Sum (1-m)^2
    }
    __syncthreads();

    // per-channel stats
    {
        int c = t & 127;
        int isx2 = t >> 7;
        const float* s = ssum + c * 12 + isx2 * 6;
        float A = s[0], Bb = s[1], Cc = s[2], Ao = s[3], Bo = s[4], Co = s[5];
        float mean_in = A / sh_nin;
        float var_in = (Cc - 2.f * mean_in * Bb + mean_in * mean_in * sh_M2) / sh_nin;
        var_in = fmaxf(var_in, 0.f);
        float mean_out = Ao / sh_nout;
        float var_out = (Co - 2.f * mean_out * Bo + mean_out * mean_out * sh_M2o) / sh_nout;
        var_out = fmaxf(var_out, 0.f);
        int vi = isx2 * 128 + c;
        v_sh[vi]       = mean_in;
        v_sh[256 + vi] = var_in;
        v_sh[512 + vi] = mean_out;
        v_sh[768 + vi] = var_out;
        if (!isx2) {
            mr_sh[c]       = mean_in;
            mr_sh[128 + c] = rsqrtf(var_in + EPS);
            mr_sh[256 + c] = mean_out;
            mr_sh[384 + c] = rsqrtf(var_out + EPS);
        }
    }
    __syncthreads();

    // GEMVs: 512 tasks (mat*128+row), 8 warps x 64 tasks, lane along j.
    {
        const float* wmats[4] = {w_in_mean, w_in_var, w_out_mean, w_out_var};
#pragma unroll 1
        for (int it = 0; it < 64; it++) {
            int task = wid * 64 + it;
            int mat = task >> 7, row = task & 127;
            const float* wrow = wmats[mat] + (size_t)row * 256;
            const float* vv = v_sh + mat * 256;
            float a = 0.f;
#pragma unroll
            for (int j = 0; j < 8; j++)
                a = fmaf(__ldg(wrow + lane + 32 * j), vv[lane + 32 * j], a);
            a = warpSum(a);
            if (lane == 0) ada_sh[task] = a;
        }
    }
    __syncthreads();

    // coefficients + counter self-reset for next graph replay
    if (t < CN) {
        int c = t;
        float mu_i = mr_sh[c], r_i = mr_sh[128 + c];
        float mu_o = mr_sh[256 + c], r_o = mr_sh[384 + c];
        float P  = r_i * ada_sh[128 + c];
        float Q  = r_o * ada_sh[384 + c];
        float k1 = ada_sh[c]       - mu_i * P;
        float k2 = ada_sh[256 + c] - mu_o * Q;
        reinterpret_cast<float4*>(g_coef)[b * CN + c] = make_float4(P, Q, k1, k2);
    }
    if (t == 0) g_cnt[b] = 0u;
}

// ---------------------------------------------------------------------------
// Kernel 2: elementwise apply, 2 float4 per thread (R2 known-good config).
// out = x1*(m^2*P + om^2*Q) + k1*m + k2*om
// ---------------------------------------------------------------------------
__global__ __launch_bounds__(256) void k_apply(const float4* __restrict__ x1,
                                               const float* __restrict__ mask,
                                               float4* __restrict__ out) {
    int ch = blockIdx.y;
    int b = ch >> 7;
    float4 coef = __ldg(&reinterpret_cast<const float4*>(g_coef)[ch]);
    float P = coef.x, Q = coef.y, k1 = coef.z, k2 = coef.w;
    const float* mb = mask + b * MHW;
    const float4* px = x1 + (size_t)ch * (HW / 4);
    float4* po = out + (size_t)ch * (HW / 4);
    int q0 = blockIdx.x * 512 + threadIdx.x;

#pragma unroll
    for (int r = 0; r < 2; r++) {
        int q = q0 + r * 256;
        float4 v = px[q];
        int midx = ((q >> 7) << 7) | ((2 * q) & 126);
        float2 mp = *reinterpret_cast<const float2*>(mb + midx);
        float xs[4] = {v.x, v.y, v.z, v.w};
        float ms[4] = {mp.x, mp.x, mp.y, mp.y};
        float os[4];
#pragma unroll
        for (int i = 0; i < 4; i++) {
            float m = ms[i], om = 1.f - m;
            float s = m * m * P + om * om * Q;
            os[i] = xs[i] * s + k1 * m + k2 * om;
        }
        po[q] = make_float4(os[0], os[1], os[2], os[3]);
    }
}

extern "C" void kernel_launch(void* const* d_in, const int* in_sizes, int n_in,
                              void* d_out, int out_size) {
    const float* x1         = (const float*)d_in[0];
    const float* x2         = (const float*)d_in[1];
    const float* mask       = (const float*)d_in[2];
    const float* w_in_mean  = (const float*)d_in[3];
    const float* w_in_var   = (const float*)d_in[4];
    const float* w_out_mean = (const float*)d_in[5];
    const float* w_out_var  = (const float*)d_in[6];
    float* out = (float*)d_out;

    k_reduce<<<NPART * NCH, 256>>>((const float4*)x1, (const float4*)x2, mask,
                                   w_in_mean, w_in_var, w_out_mean, w_out_var);
    k_apply<<<dim3(HW / 4 / 512, NCH), 256>>>((const float4*)x1, mask, (float4*)out);
}

// round 5
// speedup vs baseline: 1.0132x; 1.0132x over previous
#include <cuda_runtime.h>

#define EPS 1e-8f
#define BN 4
#define CN 128
#define HN 256
#define WN 256
#define HW (HN*WN)       // 65536
#define NCH (BN*CN)      // 512
#define MHW (128*128)    // 16384
#define NPART 4

// Scratch: per-channel partial sums (NPART parts) + final coefficients.
__device__ float g_sums[NPART * NCH * 12];
__device__ float g_coef[NCH * 4];          // per channel: P, Q, k1, k2
__device__ unsigned int g_cnt[BN];         // zero-init; self-resetting each run

__device__ __forceinline__ float warpSum(float v) {
#pragma unroll
    for (int o = 16; o; o >>= 1) v += __shfl_xor_sync(0xffffffffu, v, o);
    return v;
}

// ---------------------------------------------------------------------------
// Kernel 1: per-(b,c) partial reductions over a quarter of HW; the LAST
// finishing block of each batch computes that batch's final coefficients
// (mask sums, combine partials, stats, 4 modulation GEMVs).
//   var identity: Sum((x - mu)*m)^2 = C - 2*mu*B + mu^2*Sum(m^2)
//   with A = Sum x*m, B = Sum x*m^3, C = Sum x^2*m^4
//   final: out = x1*(m^2*P + om^2*Q) + k1*m + k2*om
// x1 default cache policy (L2-resident tail reused by k_apply, which walks
// in reverse); x2 streamed with __ldcs (read exactly once in the problem).
// NO occupancy cap — R4's __launch_bounds__(256,6) regressed this kernel.
// ---------------------------------------------------------------------------
__global__ __launch_bounds__(256) void k_reduce(const float4* __restrict__ x1,
                                                const float4* __restrict__ x2,
                                                const float* __restrict__ mask,
                                                const float* __restrict__ w_in_mean,
                                                const float* __restrict__ w_in_var,
                                                const float* __restrict__ w_out_mean,
                                                const float* __restrict__ w_out_var) {
    int ch   = blockIdx.x & (NCH - 1);
    int part = blockIdx.x >> 9;
    int b  = ch >> 7;
    const float4* p1 = x1 + (size_t)ch * (HW / 4) + part * 4096;
    const float4* p2 = x2 + (size_t)ch * (HW / 4) + part * 4096;
    const float*  mb = mask + b * MHW;
    int t = threadIdx.x;
    int lane = t & 31, wid = t >> 5;
    int qbase = part * 4096;

    float acc[12];
#pragma unroll
    for (int i = 0; i < 12; i++) acc[i] = 0.f;

#pragma unroll 1
    for (int k = 0; k < 16; k += 2) {
        int qa = t + k * 256;
        int qb = qa + 256;
        float4 v1a = p1[qa];
        float4 v2a = __ldcs(p2 + qa);
        float4 v1b = p1[qb];
        float4 v2b = __ldcs(p2 + qb);
        int qga = qbase + qa, qgb = qbase + qb;
        int ma_i = ((qga >> 7) << 7) | ((2 * qga) & 126);
        int mb_i = ((qgb >> 7) << 7) | ((2 * qgb) & 126);
        float2 mpa = *reinterpret_cast<const float2*>(mb + ma_i);
        float2 mpb = *reinterpret_cast<const float2*>(mb + mb_i);

#pragma unroll
        for (int half = 0; half < 2; half++) {
            float4 v1 = half ? v1b : v1a;
            float4 v2 = half ? v2b : v2a;
            float2 mp = half ? mpb : mpa;
            float mv[4]  = {mp.x, mp.x, mp.y, mp.y};
            float xv1[4] = {v1.x, v1.y, v1.z, v1.w};
            float xv2[4] = {v2.x, v2.y, v2.z, v2.w};
#pragma unroll
            for (int i = 0; i < 4; i++) {
                float m = mv[i], om = 1.0f - m;
                float mm = m * m, omm = om * om;
                float x = xv1[i];
                acc[0] += x * m;   float tt = x * mm;  acc[1] += tt * m;  acc[2] += tt * tt;
                acc[3] += x * om;  float t2 = x * omm; acc[4] += t2 * om; acc[5] += t2 * t2;
                x = xv2[i];
                acc[6] += x * m;   tt = x * mm;        acc[7] += tt * m;  acc[8] += tt * tt;
                acc[9] += x * om;  t2 = x * omm;       acc[10] += t2 * om; acc[11] += t2 * t2;
            }
        }
    }

    __shared__ float red[12][8];
#pragma unroll
    for (int i = 0; i < 12; i++) {
        float s = warpSum(acc[i]);
        if (lane == 0) red[i][wid] = s;
    }
    __syncthreads();
    if (wid == 0) {
#pragma unroll
        for (int i = 0; i < 12; i++) {
            float s = (lane < 8) ? red[i][lane] : 0.f;
            s = warpSum(s);
            if (lane == 0) g_sums[(size_t)(part * NCH + ch) * 12 + i] = s;
        }
    }

    // ---- last-block-finishes: per-batch final phase --------------------
    __shared__ unsigned int isLast;
    __threadfence();
    __syncthreads();
    if (t == 0) {
        unsigned int v = atomicAdd(&g_cnt[b], 1u);
        isLast = (v == (unsigned)(NPART * CN - 1)) ? 1u : 0u;
    }
    __syncthreads();
    if (!isLast) return;
    __threadfence();                    // acquire: see all g_sums writes

    __shared__ float sred[2][8];
    __shared__ float ssum[CN * 12];
    __shared__ float v_sh[4 * 256];     // GEMV input vectors per matrix
    __shared__ float mr_sh[512];        // mu_in, r_in, mu_out, r_out
    __shared__ float ada_sh[512];       // [mat*128 + c]
    __shared__ float sh_nin, sh_nout, sh_M2, sh_M2o;

    // mask sums (exact: 2x2 repeat upsample => Sum m = 4*Sum mask, etc.)
    {
        float s1 = 0, s2 = 0;
        for (int i = t; i < MHW; i += 256) { float m = mb[i]; s1 += m; s2 += m * m; }
        s1 = warpSum(s1); s2 = warpSum(s2);
        if (lane == 0) { sred[0][wid] = s1; sred[1][wid] = s2; }
    }

    // combine the NPART partial sums
    for (int id = t; id < CN * 12; id += 256) {
        int c = id / 12, i = id - c * 12;
        float v = 0.f;
#pragma unroll
        for (int p = 0; p < NPART; p++)
            v += g_sums[(size_t)(p * NCH + b * CN + c) * 12 + i];
        ssum[id] = v;
    }
    __syncthreads();

    if (t == 0) {
        float S1 = 0, S2 = 0;
        for (int i = 0; i < 8; i++) { S1 += sred[0][i]; S2 += sred[1][i]; }
        float msum = 4.f * S1, m2sum = 4.f * S2;
        sh_nin  = msum + EPS;
        sh_nout = ((float)HW - msum) + EPS;
        sh_M2   = m2sum;
        sh_M2o  = (float)HW - 2.f * msum + m2sum;   // Sum (1-m)^2
    }
    __syncthreads();

    // per-channel stats
    {
        int c = t & 127;
        int isx2 = t >> 7;
        const float* s = ssum + c * 12 + isx2 * 6;
        float A = s[0], Bb = s[1], Cc = s[2], Ao = s[3], Bo = s[4], Co = s[5];
        float mean_in = A / sh_nin;
        float var_in = (Cc - 2.f * mean_in * Bb + mean_in * mean_in * sh_M2) / sh_nin;
        var_in = fmaxf(var_in, 0.f);
        float mean_out = Ao / sh_nout;
        float var_out = (Co - 2.f * mean_out * Bo + mean_out * mean_out * sh_M2o) / sh_nout;
        var_out = fmaxf(var_out, 0.f);
        int vi = isx2 * 128 + c;
        v_sh[vi]       = mean_in;
        v_sh[256 + vi] = var_in;
        v_sh[512 + vi] = mean_out;
        v_sh[768 + vi] = var_out;
        if (!isx2) {
            mr_sh[c]       = mean_in;
            mr_sh[128 + c] = rsqrtf(var_in + EPS);
            mr_sh[256 + c] = mean_out;
            mr_sh[384 + c] = rsqrtf(var_out + EPS);
        }
    }
    __syncthreads();

    // GEMVs: 512 tasks (mat*128+row), 8 warps x 64 tasks, lane along j.
    {
        const float* wmats[4] = {w_in_mean, w_in_var, w_out_mean, w_out_var};
#pragma unroll 1
        for (int it = 0; it < 64; it++) {
            int task = wid * 64 + it;
            int mat = task >> 7, row = task & 127;
            const float* wrow = wmats[mat] + (size_t)row * 256;
            const float* vv = v_sh + mat * 256;
            float a = 0.f;
#pragma unroll
            for (int j = 0; j < 8; j++)
                a = fmaf(__ldg(wrow + lane + 32 * j), vv[lane + 32 * j], a);
            a = warpSum(a);
            if (lane == 0) ada_sh[task] = a;
        }
    }
    __syncthreads();

    // coefficients + counter self-reset for next graph replay
    if (t < CN) {
        int c = t;
        float mu_i = mr_sh[c], r_i = mr_sh[128 + c];
        float mu_o = mr_sh[256 + c], r_o = mr_sh[384 + c];
        float P  = r_i * ada_sh[128 + c];
        float Q  = r_o * ada_sh[384 + c];
        float k1 = ada_sh[c]       - mu_i * P;
        float k2 = ada_sh[256 + c] - mu_o * Q;
        reinterpret_cast<float4*>(g_coef)[b * CN + c] = make_float4(P, Q, k1, k2);
    }
    if (t == 0) g_cnt[b] = 0u;
}

// ---------------------------------------------------------------------------
// Kernel 2: elementwise apply, 2 float4 per thread (R2 measured-good body),
// traversed in REVERSE (channel and spatial block) so it starts on the
// L2 lines k_reduce touched last. Intra-block order unchanged (coalesced).
// out = x1*(m^2*P + om^2*Q) + k1*m + k2*om
// ---------------------------------------------------------------------------
__global__ __launch_bounds__(256) void k_apply(const float4* __restrict__ x1,
                                               const float* __restrict__ mask,
                                               float4* __restrict__ out) {
    int ch = (NCH - 1) - blockIdx.y;                 // reverse channel walk
    int b = ch >> 7;
    float4 coef = __ldg(&reinterpret_cast<const float4*>(g_coef)[ch]);
    float P = coef.x, Q = coef.y, k1 = coef.z, k2 = coef.w;
    const float* mb = mask + b * MHW;
    const float4* px = x1 + (size_t)ch * (HW / 4);
    float4* po = out + (size_t)ch * (HW / 4);
    int bx = (HW / 4 / 512 - 1) - blockIdx.x;        // reverse spatial walk
    int q0 = bx * 512 + threadIdx.x;

#pragma unroll
    for (int r = 0; r < 2; r++) {
        int q = q0 + r * 256;
        float4 v = px[q];
        int midx = ((q >> 7) << 7) | ((2 * q) & 126);
        float2 mp = *reinterpret_cast<const float2*>(mb + midx);
        float xs[4] = {v.x, v.y, v.z, v.w};
        float ms[4] = {mp.x, mp.x, mp.y, mp.y};
        float os[4];
#pragma unroll
        for (int i = 0; i < 4; i++) {
            float m = ms[i], om = 1.f - m;
            float s = m * m * P + om * om * Q;
            os[i] = xs[i] * s + k1 * m + k2 * om;
        }
        po[q] = make_float4(os[0], os[1], os[2], os[3]);
    }
}

extern "C" void kernel_launch(void* const* d_in, const int* in_sizes, int n_in,
                              void* d_out, int out_size) {
    const float* x1         = (const float*)d_in[0];
    const float* x2         = (const float*)d_in[1];
    const float* mask       = (const float*)d_in[2];
    const float* w_in_mean  = (const float*)d_in[3];
    const float* w_in_var   = (const float*)d_in[4];
    const float* w_out_mean = (const float*)d_in[5];
    const float* w_out_var  = (const float*)d_in[6];
    float* out = (float*)d_out;

    k_reduce<<<NPART * NCH, 256>>>((const float4*)x1, (const float4*)x2, mask,
                                   w_in_mean, w_in_var, w_out_mean, w_out_var);
    k_apply<<<dim3(HW / 4 / 512, NCH), 256>>>((const float4*)x1, mask, (float4*)out);
}

// round 6
// speedup vs baseline: 1.1684x; 1.1531x over previous
#include <cuda_runtime.h>

#define EPS 1e-8f
#define BN 4
#define CN 128
#define HN 256
#define WN 256
#define HW (HN*WN)       // 65536
#define NCH (BN*CN)      // 512
#define MHW (128*128)    // 16384
#define NPART 4

// Scratch: per-channel partial sums (NPART parts) + final coefficients.
__device__ float g_sums[NPART * NCH * 12];
__device__ float g_coef[NCH * 4];          // per channel: P, Q, k1, k2

__device__ __forceinline__ float warpSum(float v) {
#pragma unroll
    for (int o = 16; o; o >>= 1) v += __shfl_xor_sync(0xffffffffu, v, o);
    return v;
}

__device__ __forceinline__ void gdc_wait() {
    asm volatile("griddepcontrol.wait;" ::: "memory");
}
__device__ __forceinline__ void gdc_launch_dependents() {
    asm volatile("griddepcontrol.launch_dependents;" ::: "memory");
}

// ---------------------------------------------------------------------------
// Kernel 1: per-(b,c) partial reductions over a quarter of HW (R3's measured
// 48.8us configuration: batch-2 front-loaded LDG.128, no occupancy cap).
//   A = Sum x*m, B = Sum x*m^3, C = Sum x^2*m^4  per tensor/region
// x2 streamed (__ldcs, read-once); x1 default policy.
// Signals PDL dependents after publishing g_sums.
// ---------------------------------------------------------------------------
__global__ __launch_bounds__(256) void k_reduce(const float4* __restrict__ x1,
                                                const float4* __restrict__ x2,
                                                const float* __restrict__ mask) {
    int ch   = blockIdx.x & (NCH - 1);
    int part = blockIdx.x >> 9;
    int b  = ch >> 7;
    const float4* p1 = x1 + (size_t)ch * (HW / 4) + part * 4096;
    const float4* p2 = x2 + (size_t)ch * (HW / 4) + part * 4096;
    const float*  mb = mask + b * MHW;
    int t = threadIdx.x;
    int lane = t & 31, wid = t >> 5;
    int qbase = part * 4096;

    float acc[12];
#pragma unroll
    for (int i = 0; i < 12; i++) acc[i] = 0.f;

#pragma unroll 1
    for (int k = 0; k < 16; k += 2) {
        int qa = t + k * 256;
        int qb = qa + 256;
        float4 v1a = p1[qa];
        float4 v2a = __ldcs(p2 + qa);
        float4 v1b = p1[qb];
        float4 v2b = __ldcs(p2 + qb);
        int qga = qbase + qa, qgb = qbase + qb;
        int ma_i = ((qga >> 7) << 7) | ((2 * qga) & 126);
        int mb_i = ((qgb >> 7) << 7) | ((2 * qgb) & 126);
        float2 mpa = *reinterpret_cast<const float2*>(mb + ma_i);
        float2 mpb = *reinterpret_cast<const float2*>(mb + mb_i);

#pragma unroll
        for (int half = 0; half < 2; half++) {
            float4 v1 = half ? v1b : v1a;
            float4 v2 = half ? v2b : v2a;
            float2 mp = half ? mpb : mpa;
            float mv[4]  = {mp.x, mp.x, mp.y, mp.y};
            float xv1[4] = {v1.x, v1.y, v1.z, v1.w};
            float xv2[4] = {v2.x, v2.y, v2.z, v2.w};
#pragma unroll
            for (int i = 0; i < 4; i++) {
                float m = mv[i], om = 1.0f - m;
                float mm = m * m, omm = om * om;
                float x = xv1[i];
                acc[0] += x * m;   float tt = x * mm;  acc[1] += tt * m;  acc[2] += tt * tt;
                acc[3] += x * om;  float t2 = x * omm; acc[4] += t2 * om; acc[5] += t2 * t2;
                x = xv2[i];
                acc[6] += x * m;   tt = x * mm;        acc[7] += tt * m;  acc[8] += tt * tt;
                acc[9] += x * om;  t2 = x * omm;       acc[10] += t2 * om; acc[11] += t2 * t2;
            }
        }
    }

    __shared__ float red[12][8];
#pragma unroll
    for (int i = 0; i < 12; i++) {
        float s = warpSum(acc[i]);
        if (lane == 0) red[i][wid] = s;
    }
    __syncthreads();
    if (wid == 0) {
#pragma unroll
        for (int i = 0; i < 12; i++) {
            float s = (lane < 8) ? red[i][lane] : 0.f;
            s = warpSum(s);
            if (lane == 0) g_sums[(size_t)(part * NCH + ch) * 12 + i] = s;
        }
    }
    __threadfence();
    __syncthreads();
    gdc_launch_dependents();
}

// ---------------------------------------------------------------------------
// Kernel 2: stats + modulation GEMVs. grid (BN, 4 row-groups), 16 blocks.
// PRE-WAIT: per-batch mask sums (depends only on input mask) overlap with
// k_reduce's drain. POST-WAIT: combine partials, per-channel stats
// (redundant per row-group block, cheap), GEMV for this block's 32 rows x 4
// matrices (warp-per-row, lane along j - R2's measured-good layout), coefs:
//   out = x1*(m^2*P + om^2*Q) + k1*m + k2*om
// ---------------------------------------------------------------------------
__global__ __launch_bounds__(256) void k_small(const float* __restrict__ mask,
                                               const float* __restrict__ w_in_mean,
                                               const float* __restrict__ w_in_var,
                                               const float* __restrict__ w_out_mean,
                                               const float* __restrict__ w_out_var) {
    int b  = blockIdx.x;
    int cg = blockIdx.y;              // rows [cg*32, cg*32+32)
    int t = threadIdx.x;
    int lane = t & 31, wid = t >> 5;

    __shared__ float sred[2][8];
    __shared__ float ssum[CN * 12];
    __shared__ float v_sh[4 * 256];
    __shared__ float mr_sh[512];      // mu_in, r_in, mu_out, r_out
    __shared__ float ada_sh[128];     // [mat*32 + local_row]
    __shared__ float sh_nin, sh_nout, sh_M2, sh_M2o;

    // ---- pre-wait: mask sums (input-only) ----
    const float* mb = mask + b * MHW;
    {
        float s1 = 0, s2 = 0;
        for (int i = t; i < MHW; i += 256) { float m = mb[i]; s1 += m; s2 += m * m; }
        s1 = warpSum(s1); s2 = warpSum(s2);
        if (lane == 0) { sred[0][wid] = s1; sred[1][wid] = s2; }
    }
    __syncthreads();
    if (t == 0) {
        float S1 = 0, S2 = 0;
        for (int i = 0; i < 8; i++) { S1 += sred[0][i]; S2 += sred[1][i]; }
        float msum = 4.f * S1, m2sum = 4.f * S2;   // exact 2x2-repeat upsample
        sh_nin  = msum + EPS;
        sh_nout = ((float)HW - msum) + EPS;
        sh_M2   = m2sum;
        sh_M2o  = (float)HW - 2.f * msum + m2sum;  // Sum (1-m)^2
    }

    // ---- wait for k_reduce's g_sums ----
    gdc_wait();

    for (int id = t; id < CN * 12; id += 256) {
        int c = id / 12, i = id - c * 12;
        float v = 0.f;
#pragma unroll
        for (int p = 0; p < NPART; p++)
            v += g_sums[(size_t)(p * NCH + b * CN + c) * 12 + i];
        ssum[id] = v;
    }
    __syncthreads();

    // per-channel stats (all 128 channels; needed as GEMV input vector)
    {
        int c = t & 127;
        int isx2 = t >> 7;
        const float* s = ssum + c * 12 + isx2 * 6;
        float A = s[0], Bb = s[1], Cc = s[2], Ao = s[3], Bo = s[4], Co = s[5];
        float mean_in = A / sh_nin;
        float var_in = (Cc - 2.f * mean_in * Bb + mean_in * mean_in * sh_M2) / sh_nin;
        var_in = fmaxf(var_in, 0.f);
        float mean_out = Ao / sh_nout;
        float var_out = (Co - 2.f * mean_out * Bo + mean_out * mean_out * sh_M2o) / sh_nout;
        var_out = fmaxf(var_out, 0.f);
        int vi = isx2 * 128 + c;
        v_sh[vi]       = mean_in;
        v_sh[256 + vi] = var_in;
        v_sh[512 + vi] = mean_out;
        v_sh[768 + vi] = var_out;
        if (!isx2) {
            mr_sh[c]       = mean_in;
            mr_sh[128 + c] = rsqrtf(var_in + EPS);
            mr_sh[256 + c] = mean_out;
            mr_sh[384 + c] = rsqrtf(var_out + EPS);
        }
    }
    __syncthreads();

    // GEMVs for this block's 32 rows x 4 matrices
    {
        const float* wmats[4] = {w_in_mean, w_in_var, w_out_mean, w_out_var};
#pragma unroll
        for (int it = 0; it < 16; it++) {
            int task = wid * 16 + it;          // 0..127 == mat*32 + lr
            int mat = task >> 5, lr = task & 31;
            const float* wrow = wmats[mat] + (size_t)(cg * 32 + lr) * 256;
            const float* vv = v_sh + mat * 256;
            float a = 0.f;
#pragma unroll
            for (int j = 0; j < 8; j++)
                a = fmaf(__ldg(wrow + lane + 32 * j), vv[lane + 32 * j], a);
            a = warpSum(a);
            if (lane == 0) ada_sh[task] = a;
        }
    }
    __syncthreads();

    if (t < 32) {
        int c = cg * 32 + t;
        float mu_i = mr_sh[c], r_i = mr_sh[128 + c];
        float mu_o = mr_sh[256 + c], r_o = mr_sh[384 + c];
        float P  = r_i * ada_sh[32 + t];          // in_var
        float Q  = r_o * ada_sh[96 + t];          // out_var
        float k1 = ada_sh[t]      - mu_i * P;     // in_mean
        float k2 = ada_sh[64 + t] - mu_o * Q;     // out_mean
        reinterpret_cast<float4*>(g_coef)[b * CN + c] = make_float4(P, Q, k1, k2);
    }
    __threadfence();
    __syncthreads();
    gdc_launch_dependents();
}

// ---------------------------------------------------------------------------
// Kernel 3: elementwise apply (R2's measured 36.4us body). PRE-WAIT: issue
// x1 + mask loads (input-only); POST-WAIT: read g_coef, compute, store.
// out = x1*(m^2*P + om^2*Q) + k1*m + k2*om
// ---------------------------------------------------------------------------
__global__ __launch_bounds__(256) void k_apply(const float4* __restrict__ x1,
                                               const float* __restrict__ mask,
                                               float4* __restrict__ out) {
    int ch = blockIdx.y;
    int b = ch >> 7;
    const float* mb = mask + b * MHW;
    const float4* px = x1 + (size_t)ch * (HW / 4);
    float4* po = out + (size_t)ch * (HW / 4);
    int q0 = blockIdx.x * 512 + threadIdx.x;

    // pre-wait independent loads
    float4 v0 = px[q0];
    float4 v1 = px[q0 + 256];
    int mi0 = ((q0 >> 7) << 7) | ((2 * q0) & 126);
    int q1 = q0 + 256;
    int mi1 = ((q1 >> 7) << 7) | ((2 * q1) & 126);
    float2 mp0 = *reinterpret_cast<const float2*>(mb + mi0);
    float2 mp1 = *reinterpret_cast<const float2*>(mb + mi1);

    gdc_wait();

    float4 coef = __ldg(&reinterpret_cast<const float4*>(g_coef)[ch]);
    float P = coef.x, Q = coef.y, k1 = coef.z, k2 = coef.w;

#pragma unroll
    for (int r = 0; r < 2; r++) {
        int q = r ? q1 : q0;
        float4 v = r ? v1 : v0;
        float2 mp = r ? mp1 : mp0;
        float xs[4] = {v.x, v.y, v.z, v.w};
        float ms[4] = {mp.x, mp.x, mp.y, mp.y};
        float os[4];
#pragma unroll
        for (int i = 0; i < 4; i++) {
            float m = ms[i], om = 1.f - m;
            float s = m * m * P + om * om * Q;
            os[i] = xs[i] * s + k1 * m + k2 * om;
        }
        po[q] = make_float4(os[0], os[1], os[2], os[3]);
    }
}

extern "C" void kernel_launch(void* const* d_in, const int* in_sizes, int n_in,
                              void* d_out, int out_size) {
    const float* x1         = (const float*)d_in[0];
    const float* x2         = (const float*)d_in[1];
    const float* mask       = (const float*)d_in[2];
    const float* w_in_mean  = (const float*)d_in[3];
    const float* w_in_var   = (const float*)d_in[4];
    const float* w_out_mean = (const float*)d_in[5];
    const float* w_out_var  = (const float*)d_in[6];
    float* out = (float*)d_out;

    // 1) reduce — plain launch
    k_reduce<<<NPART * NCH, 256>>>((const float4*)x1, (const float4*)x2, mask);

    // 2) stats+gemv — PDL consumer of reduce
    {
        cudaLaunchConfig_t cfg = {};
        cfg.gridDim = dim3(BN, 4);
        cfg.blockDim = dim3(256);
        cudaLaunchAttribute attr[1];
        attr[0].id = cudaLaunchAttributeProgrammaticStreamSerialization;
        attr[0].val.programmaticStreamSerializationAllowed = 1;
        cfg.attrs = attr;
        cfg.numAttrs = 1;
        cudaLaunchKernelEx(&cfg, k_small, mask, w_in_mean, w_in_var, w_out_mean, w_out_var);
    }

    // 3) apply — PDL consumer of k_small
    {
        cudaLaunchConfig_t cfg = {};
        cfg.gridDim = dim3(HW / 4 / 512, NCH);
        cfg.blockDim = dim3(256);
        cudaLaunchAttribute attr[1];
        attr[0].id = cudaLaunchAttributeProgrammaticStreamSerialization;
        attr[0].val.programmaticStreamSerializationAllowed = 1;
        cfg.attrs = attr;
        cfg.numAttrs = 1;
        cudaLaunchKernelEx(&cfg, k_apply, (const float4*)x1, mask, (float4*)out);
    }
}

// round 7
// speedup vs baseline: 1.2290x; 1.0519x over previous
#include <cuda_runtime.h>

#define EPS 1e-8f
#define BN 4
#define CN 128
#define HN 256
#define WN 256
#define HW (HN*WN)       // 65536
#define NCH (BN*CN)      // 512
#define MHW (128*128)    // 16384
#define NPART 4

// Scratch: per-channel partial sums (NPART parts) + final coefficients.
__device__ float g_sums[NPART * NCH * 12];
__device__ float g_coef[NCH * 4];          // per channel: P, Q, k1, k2

__device__ __forceinline__ float warpSum(float v) {
#pragma unroll
    for (int o = 16; o; o >>= 1) v += __shfl_xor_sync(0xffffffffu, v, o);
    return v;
}

__device__ __forceinline__ void gdc_wait() {
    asm volatile("griddepcontrol.wait;" ::: "memory");
}
__device__ __forceinline__ void gdc_launch_dependents() {
    asm volatile("griddepcontrol.launch_dependents;" ::: "memory");
}

// ---------------------------------------------------------------------------
// Kernel 1: per-(b,c) partial reductions over a quarter of HW.
//   A = Sum x*m, B = Sum x*m^3, C = Sum x^2*m^4  per tensor/region
// Batch-4 front-loaded LDG.128 (8 loads in flight) with __ldcs on BOTH x1
// and x2 (evict-first streaming; R3/R6 A-B showed default-policy x1 costs
// ~4us here and buys nothing downstream). Signals PDL dependents at end.
// ---------------------------------------------------------------------------
__global__ __launch_bounds__(256) void k_reduce(const float4* __restrict__ x1,
                                                const float4* __restrict__ x2,
                                                const float* __restrict__ mask) {
    int ch   = blockIdx.x & (NCH - 1);
    int part = blockIdx.x >> 9;
    int b  = ch >> 7;
    const float4* p1 = x1 + (size_t)ch * (HW / 4) + part * 4096;
    const float4* p2 = x2 + (size_t)ch * (HW / 4) + part * 4096;
    const float*  mb = mask + b * MHW;
    int t = threadIdx.x;
    int lane = t & 31, wid = t >> 5;
    int qbase = part * 4096;

    float acc[12];
#pragma unroll
    for (int i = 0; i < 12; i++) acc[i] = 0.f;

#pragma unroll 1
    for (int k = 0; k < 16; k += 4) {
        float4 v1[4], v2[4];
        float2 mp[4];
#pragma unroll
        for (int u = 0; u < 4; u++) {
            int q = t + (k + u) * 256;
            v1[u] = __ldcs(p1 + q);
            v2[u] = __ldcs(p2 + q);
        }
#pragma unroll
        for (int u = 0; u < 4; u++) {
            int qg = qbase + t + (k + u) * 256;
            int mi = ((qg >> 7) << 7) | ((2 * qg) & 126);
            mp[u] = *reinterpret_cast<const float2*>(mb + mi);
        }
#pragma unroll
        for (int u = 0; u < 4; u++) {
            float mv[4]  = {mp[u].x, mp[u].x, mp[u].y, mp[u].y};
            float xv1[4] = {v1[u].x, v1[u].y, v1[u].z, v1[u].w};
            float xv2[4] = {v2[u].x, v2[u].y, v2[u].z, v2[u].w};
#pragma unroll
            for (int i = 0; i < 4; i++) {
                float m = mv[i], om = 1.0f - m;
                float mm = m * m, omm = om * om;
                float x = xv1[i];
                acc[0] += x * m;   float tt = x * mm;  acc[1] += tt * m;  acc[2] += tt * tt;
                acc[3] += x * om;  float t2 = x * omm; acc[4] += t2 * om; acc[5] += t2 * t2;
                x = xv2[i];
                acc[6] += x * m;   tt = x * mm;        acc[7] += tt * m;  acc[8] += tt * tt;
                acc[9] += x * om;  t2 = x * omm;       acc[10] += t2 * om; acc[11] += t2 * t2;
            }
        }
    }

    __shared__ float red[12][8];
#pragma unroll
    for (int i = 0; i < 12; i++) {
        float s = warpSum(acc[i]);
        if (lane == 0) red[i][wid] = s;
    }
    __syncthreads();
    if (wid == 0) {
#pragma unroll
        for (int i = 0; i < 12; i++) {
            float s = (lane < 8) ? red[i][lane] : 0.f;
            s = warpSum(s);
            if (lane == 0) g_sums[(size_t)(part * NCH + ch) * 12 + i] = s;
        }
    }
    __threadfence();
    __syncthreads();
    gdc_launch_dependents();
}

// ---------------------------------------------------------------------------
// Kernel 2: stats + modulation GEMVs. grid (BN, 4 row-groups), 16 blocks.
// PRE-WAIT: per-batch mask sums (input-only) overlap with k_reduce's drain.
// POST-WAIT: combine partials, per-channel stats, GEMV (warp-per-row,
// lane along j), coefficients:  out = x1*(m^2*P + om^2*Q) + k1*m + k2*om
// ---------------------------------------------------------------------------
__global__ __launch_bounds__(256) void k_small(const float* __restrict__ mask,
                                               const float* __restrict__ w_in_mean,
                                               const float* __restrict__ w_in_var,
                                               const float* __restrict__ w_out_mean,
                                               const float* __restrict__ w_out_var) {
    int b  = blockIdx.x;
    int cg = blockIdx.y;              // rows [cg*32, cg*32+32)
    int t = threadIdx.x;
    int lane = t & 31, wid = t >> 5;

    __shared__ float sred[2][8];
    __shared__ float ssum[CN * 12];
    __shared__ float v_sh[4 * 256];
    __shared__ float mr_sh[512];      // mu_in, r_in, mu_out, r_out
    __shared__ float ada_sh[128];     // [mat*32 + local_row]
    __shared__ float sh_nin, sh_nout, sh_M2, sh_M2o;

    // ---- pre-wait: mask sums (exact: 2x2-repeat upsample) ----
    const float* mb = mask + b * MHW;
    {
        float s1 = 0, s2 = 0;
        for (int i = t; i < MHW; i += 256) { float m = mb[i]; s1 += m; s2 += m * m; }
        s1 = warpSum(s1); s2 = warpSum(s2);
        if (lane == 0) { sred[0][wid] = s1; sred[1][wid] = s2; }
    }
    __syncthreads();
    if (t == 0) {
        float S1 = 0, S2 = 0;
        for (int i = 0; i < 8; i++) { S1 += sred[0][i]; S2 += sred[1][i]; }
        float msum = 4.f * S1, m2sum = 4.f * S2;
        sh_nin  = msum + EPS;
        sh_nout = ((float)HW - msum) + EPS;
        sh_M2   = m2sum;
        sh_M2o  = (float)HW - 2.f * msum + m2sum;  // Sum (1-m)^2
    }

    // ---- wait for k_reduce's g_sums ----
    gdc_wait();

    for (int id = t; id < CN * 12; id += 256) {
        int c = id / 12, i = id - c * 12;
        float v = 0.f;
#pragma unroll
        for (int p = 0; p < NPART; p++)
            v += g_sums[(size_t)(p * NCH + b * CN + c) * 12 + i];
        ssum[id] = v;
    }
    __syncthreads();

    {
        int c = t & 127;
        int isx2 = t >> 7;
        const float* s = ssum + c * 12 + isx2 * 6;
        float A = s[0], Bb = s[1], Cc = s[2], Ao = s[3], Bo = s[4], Co = s[5];
        float mean_in = A / sh_nin;
        float var_in = (Cc - 2.f * mean_in * Bb + mean_in * mean_in * sh_M2) / sh_nin;
        var_in = fmaxf(var_in, 0.f);
        float mean_out = Ao / sh_nout;
        float var_out = (Co - 2.f * mean_out * Bo + mean_out * mean_out * sh_M2o) / sh_nout;
        var_out = fmaxf(var_out, 0.f);
        int vi = isx2 * 128 + c;
        v_sh[vi]       = mean_in;
        v_sh[256 + vi] = var_in;
        v_sh[512 + vi] = mean_out;
        v_sh[768 + vi] = var_out;
        if (!isx2) {
            mr_sh[c]       = mean_in;
            mr_sh[128 + c] = rsqrtf(var_in + EPS);
            mr_sh[256 + c] = mean_out;
            mr_sh[384 + c] = rsqrtf(var_out + EPS);
        }
    }
    __syncthreads();

    {
        const float* wmats[4] = {w_in_mean, w_in_var, w_out_mean, w_out_var};
#pragma unroll
        for (int it = 0; it < 16; it++) {
            int task = wid * 16 + it;          // 0..127 == mat*32 + lr
            int mat = task >> 5, lr = task & 31;
            const float* wrow = wmats[mat] + (size_t)(cg * 32 + lr) * 256;
            const float* vv = v_sh + mat * 256;
            float a = 0.f;
#pragma unroll
            for (int j = 0; j < 8; j++)
                a = fmaf(__ldg(wrow + lane + 32 * j), vv[lane + 32 * j], a);
            a = warpSum(a);
            if (lane == 0) ada_sh[task] = a;
        }
    }
    __syncthreads();

    if (t < 32) {
        int c = cg * 32 + t;
        float mu_i = mr_sh[c], r_i = mr_sh[128 + c];
        float mu_o = mr_sh[256 + c], r_o = mr_sh[384 + c];
        float P  = r_i * ada_sh[32 + t];          // in_var
        float Q  = r_o * ada_sh[96 + t];          // out_var
        float k1 = ada_sh[t]      - mu_i * P;     // in_mean
        float k2 = ada_sh[64 + t] - mu_o * Q;     // out_mean
        reinterpret_cast<float4*>(g_coef)[b * CN + c] = make_float4(P, Q, k1, k2);
    }
    __threadfence();
    __syncthreads();
    gdc_launch_dependents();
}

// ---------------------------------------------------------------------------
// Kernel 3: elementwise apply (measured 36.4us body). PRE-WAIT: issue
// x1 + mask loads (input-only); POST-WAIT: read g_coef, compute, store.
// out = x1*(m^2*P + om^2*Q) + k1*m + k2*om
// ---------------------------------------------------------------------------
__global__ __launch_bounds__(256) void k_apply(const float4* __restrict__ x1,
                                               const float* __restrict__ mask,
                                               float4* __restrict__ out) {
    int ch = blockIdx.y;
    int b = ch >> 7;
    const float* mb = mask + b * MHW;
    const float4* px = x1 + (size_t)ch * (HW / 4);
    float4* po = out + (size_t)ch * (HW / 4);
    int q0 = blockIdx.x * 512 + threadIdx.x;

    // pre-wait independent loads
    float4 v0 = px[q0];
    float4 v1 = px[q0 + 256];
    int mi0 = ((q0 >> 7) << 7) | ((2 * q0) & 126);
    int q1 = q0 + 256;
    int mi1 = ((q1 >> 7) << 7) | ((2 * q1) & 126);
    float2 mp0 = *reinterpret_cast<const float2*>(mb + mi0);
    float2 mp1 = *reinterpret_cast<const float2*>(mb + mi1);

    gdc_wait();

    float4 coef = __ldg(&reinterpret_cast<const float4*>(g_coef)[ch]);
    float P = coef.x, Q = coef.y, k1 = coef.z, k2 = coef.w;

#pragma unroll
    for (int r = 0; r < 2; r++) {
        int q = r ? q1 : q0;
        float4 v = r ? v1 : v0;
        float2 mp = r ? mp1 : mp0;
        float xs[4] = {v.x, v.y, v.z, v.w};
        float ms[4] = {mp.x, mp.x, mp.y, mp.y};
        float os[4];
#pragma unroll
        for (int i = 0; i < 4; i++) {
            float m = ms[i], om = 1.f - m;
            float s = m * m * P + om * om * Q;
            os[i] = xs[i] * s + k1 * m + k2 * om;
        }
        po[q] = make_float4(os[0], os[1], os[2], os[3]);
    }
}

extern "C" void kernel_launch(void* const* d_in, const int* in_sizes, int n_in,
                              void* d_out, int out_size) {
    const float* x1         = (const float*)d_in[0];
    const float* x2         = (const float*)d_in[1];
    const float* mask       = (const float*)d_in[2];
    const float* w_in_mean  = (const float*)d_in[3];
    const float* w_in_var   = (const float*)d_in[4];
    const float* w_out_mean = (const float*)d_in[5];
    const float* w_out_var  = (const float*)d_in[6];
    float* out = (float*)d_out;

    // 1) reduce — plain launch
    k_reduce<<<NPART * NCH, 256>>>((const float4*)x1, (const float4*)x2, mask);

    // 2) stats+gemv — PDL consumer of reduce
    {
        cudaLaunchConfig_t cfg = {};
        cfg.gridDim = dim3(BN, 4);
        cfg.blockDim = dim3(256);
        cudaLaunchAttribute attr[1];
        attr[0].id = cudaLaunchAttributeProgrammaticStreamSerialization;
        attr[0].val.programmaticStreamSerializationAllowed = 1;
        cfg.attrs = attr;
        cfg.numAttrs = 1;
        cudaLaunchKernelEx(&cfg, k_small, mask, w_in_mean, w_in_var, w_out_mean, w_out_var);
    }

    // 3) apply — PDL consumer of k_small
    {
        cudaLaunchConfig_t cfg = {};
        cfg.gridDim = dim3(HW / 4 / 512, NCH);
        cfg.blockDim = dim3(256);
        cudaLaunchAttribute attr[1];
        attr[0].id = cudaLaunchAttributeProgrammaticStreamSerialization;
        attr[0].val.programmaticStreamSerializationAllowed = 1;
        cfg.attrs = attr;
        cfg.numAttrs = 1;
        cudaLaunchKernelEx(&cfg, k_apply, (const float4*)x1, mask, (float4*)out);
    }
}

// round 8
// speedup vs baseline: 1.2677x; 1.0315x over previous
#include <cuda_runtime.h>

#define EPS 1e-8f
#define BN 4
#define CN 128
#define HN 256
#define WN 256
#define HW (HN*WN)       // 65536
#define NCH (BN*CN)      // 512
#define MHW (128*128)    // 16384
#define NPART 4

// Scratch: per-channel partial sums (NPART parts) + final coefficients.
__device__ float g_sums[NPART * NCH * 12];
__device__ float g_coef[NCH * 4];          // per channel: P, Q, k1, k2

__device__ __forceinline__ float warpSum(float v) {
#pragma unroll
    for (int o = 16; o; o >>= 1) v += __shfl_xor_sync(0xffffffffu, v, o);
    return v;
}

__device__ __forceinline__ void gdc_wait() {
    asm volatile("griddepcontrol.wait;" ::: "memory");
}
__device__ __forceinline__ void gdc_launch_dependents() {
    asm volatile("griddepcontrol.launch_dependents;" ::: "memory");
}

// ---------------------------------------------------------------------------
// Kernel 1: per-(b,c) partial reductions over a quarter of HW.
//   A = Sum x*m, B = Sum x*m^3, C = Sum x^2*m^4   per tensor/region.
// KEY: mask is a 2x2 nearest upsample, so 4 x-elements share each mask
// scalar. Each thread loads the (q, q+64) vertical row-pair: its 2 x1
// float4s + 2 x2 float4s share ONE mask float2. Factored accumulation
// (sx = sum of 4 x, sq = sum of 4 x^2, then 3 FMAs per region) cuts fp
// ops/byte ~3x vs the per-element form — this kernel was compute-overhead
// bound at 65% DRAM, not MLP-bound (R6/R7 A-B evidence).
// ---------------------------------------------------------------------------
__global__ __launch_bounds__(256) void k_reduce(const float4* __restrict__ x1,
                                                const float4* __restrict__ x2,
                                                const float* __restrict__ mask) {
    int ch   = blockIdx.x & (NCH - 1);
    int part = blockIdx.x >> 9;
    int b  = ch >> 7;
    const float4* p1 = x1 + (size_t)ch * (HW / 4) + part * 4096;
    const float4* p2 = x2 + (size_t)ch * (HW / 4) + part * 4096;
    const float*  mb = mask + b * MHW;
    int t = threadIdx.x;
    int lane = t & 31, wid = t >> 5;
    int col = t & 63;                 // float4 column within x row (0..63)
    int rpl0 = t >> 6;                // local row-pair slot (0..3)

    float acc[12];
#pragma unroll
    for (int i = 0; i < 12; i++) acc[i] = 0.f;

#pragma unroll 1
    for (int k = 0; k < 8; k++) {
        int rp = k * 4 + rpl0;        // local row-pair 0..31 within part
        int q0 = rp * 128 + col;      // x row 2*rp
        int q1 = q0 + 64;             // x row 2*rp+1 (same mask row)
        // front-loaded loads: 4x LDG.128 + 1x LDG.64
        float4 xa = __ldcs(p1 + q0);
        float4 xb = __ldcs(p1 + q1);
        float4 ya = __ldcs(p2 + q0);
        float4 yb = __ldcs(p2 + q1);
        int mrow = part * 32 + rp;
        float2 mp = *reinterpret_cast<const float2*>(mb + mrow * 128 + 2 * col);

#pragma unroll
        for (int hsel = 0; hsel < 2; hsel++) {
            float m = hsel ? mp.y : mp.x;
            float e0 = hsel ? xa.z : xa.x, e1 = hsel ? xa.w : xa.y;
            float e2 = hsel ? xb.z : xb.x, e3 = hsel ? xb.w : xb.y;
            float f0 = hsel ? ya.z : ya.x, f1 = hsel ? ya.w : ya.y;
            float f2 = hsel ? yb.z : yb.x, f3 = hsel ? yb.w : yb.y;

            float om = 1.0f - m;
            float m2 = m * m, om2 = om * om;
            float m4 = m2 * m2, om4 = om2 * om2;

            float sx = (e0 + e1) + (e2 + e3);
            float sq = fmaf(e0, e0, fmaf(e1, e1, fmaf(e2, e2, e3 * e3)));
            acc[0] = fmaf(sx, m, acc[0]);
            acc[1] = fmaf(sx * m, m2, acc[1]);
            acc[2] = fmaf(sq, m4, acc[2]);
            acc[3] = fmaf(sx, om, acc[3]);
            acc[4] = fmaf(sx * om, om2, acc[4]);
            acc[5] = fmaf(sq, om4, acc[5]);

            float sy = (f0 + f1) + (f2 + f3);
            float sr = fmaf(f0, f0, fmaf(f1, f1, fmaf(f2, f2, f3 * f3)));
            acc[6]  = fmaf(sy, m, acc[6]);
            acc[7]  = fmaf(sy * m, m2, acc[7]);
            acc[8]  = fmaf(sr, m4, acc[8]);
            acc[9]  = fmaf(sy, om, acc[9]);
            acc[10] = fmaf(sy * om, om2, acc[10]);
            acc[11] = fmaf(sr, om4, acc[11]);
        }
    }

    __shared__ float red[12][8];
#pragma unroll
    for (int i = 0; i < 12; i++) {
        float s = warpSum(acc[i]);
        if (lane == 0) red[i][wid] = s;
    }
    __syncthreads();
    if (wid == 0) {
#pragma unroll
        for (int i = 0; i < 12; i++) {
            float s = (lane < 8) ? red[i][lane] : 0.f;
            s = warpSum(s);
            if (lane == 0) g_sums[(size_t)(part * NCH + ch) * 12 + i] = s;
        }
    }
    __threadfence();
    __syncthreads();
    gdc_launch_dependents();
}

// ---------------------------------------------------------------------------
// Kernel 2: stats + modulation GEMVs. grid (BN, 4 row-groups), 16 blocks.
// PRE-WAIT: per-batch mask sums (input-only) overlap with k_reduce's drain.
// POST-WAIT: combine partials, per-channel stats, GEMV (warp-per-row,
// lane along j), coefficients:  out = x1*(m^2*P + om^2*Q) + k1*m + k2*om
// ---------------------------------------------------------------------------
__global__ __launch_bounds__(256) void k_small(const float* __restrict__ mask,
                                               const float* __restrict__ w_in_mean,
                                               const float* __restrict__ w_in_var,
                                               const float* __restrict__ w_out_mean,
                                               const float* __restrict__ w_out_var) {
    int b  = blockIdx.x;
    int cg = blockIdx.y;              // rows [cg*32, cg*32+32)
    int t = threadIdx.x;
    int lane = t & 31, wid = t >> 5;

    __shared__ float sred[2][8];
    __shared__ float ssum[CN * 12];
    __shared__ float v_sh[4 * 256];
    __shared__ float mr_sh[512];      // mu_in, r_in, mu_out, r_out
    __shared__ float ada_sh[128];     // [mat*32 + local_row]
    __shared__ float sh_nin, sh_nout, sh_M2, sh_M2o;

    // ---- pre-wait: mask sums (exact: 2x2-repeat upsample) ----
    const float* mb = mask + b * MHW;
    {
        float s1 = 0, s2 = 0;
        for (int i = t; i < MHW; i += 256) { float m = mb[i]; s1 += m; s2 += m * m; }
        s1 = warpSum(s1); s2 = warpSum(s2);
        if (lane == 0) { sred[0][wid] = s1; sred[1][wid] = s2; }
    }
    __syncthreads();
    if (t == 0) {
        float S1 = 0, S2 = 0;
        for (int i = 0; i < 8; i++) { S1 += sred[0][i]; S2 += sred[1][i]; }
        float msum = 4.f * S1, m2sum = 4.f * S2;
        sh_nin  = msum + EPS;
        sh_nout = ((float)HW - msum) + EPS;
        sh_M2   = m2sum;
        sh_M2o  = (float)HW - 2.f * msum + m2sum;  // Sum (1-m)^2
    }

    // ---- wait for k_reduce's g_sums ----
    gdc_wait();

    for (int id = t; id < CN * 12; id += 256) {
        int c = id / 12, i = id - c * 12;
        float v = 0.f;
#pragma unroll
        for (int p = 0; p < NPART; p++)
            v += g_sums[(size_t)(p * NCH + b * CN + c) * 12 + i];
        ssum[id] = v;
    }
    __syncthreads();

    {
        int c = t & 127;
        int isx2 = t >> 7;
        const float* s = ssum + c * 12 + isx2 * 6;
        float A = s[0], Bb = s[1], Cc = s[2], Ao = s[3], Bo = s[4], Co = s[5];
        float mean_in = A / sh_nin;
        float var_in = (Cc - 2.f * mean_in * Bb + mean_in * mean_in * sh_M2) / sh_nin;
        var_in = fmaxf(var_in, 0.f);
        float mean_out = Ao / sh_nout;
        float var_out = (Co - 2.f * mean_out * Bo + mean_out * mean_out * sh_M2o) / sh_nout;
        var_out = fmaxf(var_out, 0.f);
        int vi = isx2 * 128 + c;
        v_sh[vi]       = mean_in;
        v_sh[256 + vi] = var_in;
        v_sh[512 + vi] = mean_out;
        v_sh[768 + vi] = var_out;
        if (!isx2) {
            mr_sh[c]       = mean_in;
            mr_sh[128 + c] = rsqrtf(var_in + EPS);
            mr_sh[256 + c] = mean_out;
            mr_sh[384 + c] = rsqrtf(var_out + EPS);
        }
    }
    __syncthreads();

    {
        const float* wmats[4] = {w_in_mean, w_in_var, w_out_mean, w_out_var};
#pragma unroll
        for (int it = 0; it < 16; it++) {
            int task = wid * 16 + it;          // 0..127 == mat*32 + lr
            int mat = task >> 5, lr = task & 31;
            const float* wrow = wmats[mat] + (size_t)(cg * 32 + lr) * 256;
            const float* vv = v_sh + mat * 256;
            float a = 0.f;
#pragma unroll
            for (int j = 0; j < 8; j++)
                a = fmaf(__ldg(wrow + lane + 32 * j), vv[lane + 32 * j], a);
            a = warpSum(a);
            if (lane == 0) ada_sh[task] = a;
        }
    }
    __syncthreads();

    if (t < 32) {
        int c = cg * 32 + t;
        float mu_i = mr_sh[c], r_i = mr_sh[128 + c];
        float mu_o = mr_sh[256 + c], r_o = mr_sh[384 + c];
        float P  = r_i * ada_sh[32 + t];          // in_var
        float Q  = r_o * ada_sh[96 + t];          // out_var
        float k1 = ada_sh[t]      - mu_i * P;     // in_mean
        float k2 = ada_sh[64 + t] - mu_o * Q;     // out_mean
        reinterpret_cast<float4*>(g_coef)[b * CN + c] = make_float4(P, Q, k1, k2);
    }
    __threadfence();
    __syncthreads();
    gdc_launch_dependents();
}

// ---------------------------------------------------------------------------
// Kernel 3: elementwise apply (measured 36.4us body). PRE-WAIT: issue
// x1 + mask loads (input-only); POST-WAIT: read g_coef, compute, store.
// out = x1*(m^2*P + om^2*Q) + k1*m + k2*om
// ---------------------------------------------------------------------------
__global__ __launch_bounds__(256) void k_apply(const float4* __restrict__ x1,
                                               const float* __restrict__ mask,
                                               float4* __restrict__ out) {
    int ch = blockIdx.y;
    int b = ch >> 7;
    const float* mb = mask + b * MHW;
    const float4* px = x1 + (size_t)ch * (HW / 4);
    float4* po = out + (size_t)ch * (HW / 4);
    int q0 = blockIdx.x * 512 + threadIdx.x;

    // pre-wait independent loads
    float4 v0 = px[q0];
    float4 v1 = px[q0 + 256];
    int mi0 = ((q0 >> 7) << 7) | ((2 * q0) & 126);
    int q1 = q0 + 256;
    int mi1 = ((q1 >> 7) << 7) | ((2 * q1) & 126);
    float2 mp0 = *reinterpret_cast<const float2*>(mb + mi0);
    float2 mp1 = *reinterpret_cast<const float2*>(mb + mi1);

    gdc_wait();

    float4 coef = __ldg(&reinterpret_cast<const float4*>(g_coef)[ch]);
    float P = coef.x, Q = coef.y, k1 = coef.z, k2 = coef.w;

#pragma unroll
    for (int r = 0; r < 2; r++) {
        int q = r ? q1 : q0;
        float4 v = r ? v1 : v0;
        float2 mp = r ? mp1 : mp0;
        float xs[4] = {v.x, v.y, v.z, v.w};
        float ms[4] = {mp.x, mp.x, mp.y, mp.y};
        float os[4];
#pragma unroll
        for (int i = 0; i < 4; i++) {
            float m = ms[i], om = 1.f - m;
            float s = m * m * P + om * om * Q;
            os[i] = xs[i] * s + k1 * m + k2 * om;
        }
        po[q] = make_float4(os[0], os[1], os[2], os[3]);
    }
}

extern "C" void kernel_launch(void* const* d_in, const int* in_sizes, int n_in,
                              void* d_out, int out_size) {
    const float* x1         = (const float*)d_in[0];
    const float* x2         = (const float*)d_in[1];
    const float* mask       = (const float*)d_in[2];
    const float* w_in_mean  = (const float*)d_in[3];
    const float* w_in_var   = (const float*)d_in[4];
    const float* w_out_mean = (const float*)d_in[5];
    const float* w_out_var  = (const float*)d_in[6];
    float* out = (float*)d_out;

    // 1) reduce — plain launch
    k_reduce<<<NPART * NCH, 256>>>((const float4*)x1, (const float4*)x2, mask);

    // 2) stats+gemv — PDL consumer of reduce
    {
        cudaLaunchConfig_t cfg = {};
        cfg.gridDim = dim3(BN, 4);
        cfg.blockDim = dim3(256);
        cudaLaunchAttribute attr[1];
        attr[0].id = cudaLaunchAttributeProgrammaticStreamSerialization;
        attr[0].val.programmaticStreamSerializationAllowed = 1;
        cfg.attrs = attr;
        cfg.numAttrs = 1;
        cudaLaunchKernelEx(&cfg, k_small, mask, w_in_mean, w_in_var, w_out_mean, w_out_var);
    }

    // 3) apply — PDL consumer of k_small
    {
        cudaLaunchConfig_t cfg = {};
        cfg.gridDim = dim3(HW / 4 / 512, NCH);
        cfg.blockDim = dim3(256);
        cudaLaunchAttribute attr[1];
        attr[0].id = cudaLaunchAttributeProgrammaticStreamSerialization;
        attr[0].val.programmaticStreamSerializationAllowed = 1;
        cfg.attrs = attr;
        cfg.numAttrs = 1;
        cudaLaunchKernelEx(&cfg, k_apply, (const float4*)x1, mask, (float4*)out);
    }
}

// round 9
// speedup vs baseline: 1.3115x; 1.0346x over previous
#include <cuda_runtime.h>

#define EPS 1e-8f
#define BN 4
#define CN 128
#define HN 256
#define WN 256
#define HW (HN*WN)       // 65536
#define NCH (BN*CN)      // 512
#define MHW (128*128)    // 16384
#define NPART 4

// Scratch: per-channel partial sums (NPART parts) + final coefficients.
__device__ float g_sums[NPART * NCH * 12];
__device__ float g_coef[NCH * 4];          // per channel: P, Q, k1, k2

__device__ __forceinline__ float warpSum(float v) {
#pragma unroll
    for (int o = 16; o; o >>= 1) v += __shfl_xor_sync(0xffffffffu, v, o);
    return v;
}

__device__ __forceinline__ void gdc_wait() {
    asm volatile("griddepcontrol.wait;" ::: "memory");
}
__device__ __forceinline__ void gdc_launch_dependents() {
    asm volatile("griddepcontrol.launch_dependents;" ::: "memory");
}

// ---------------------------------------------------------------------------
// Kernel 1: per-(b,c) partial reductions, SPLIT BY TENSOR: each block does
// x1-only or x2-only over a quarter of HW. 6 accumulators + 2 LDG.128 in
// flight -> fits 32 regs / 8 blocks/SM (R8 showed occupancy, not compute or
// MLP, was the remaining limiter at 69% DRAM).
//   A = Sum x*m, B = Sum x*m^3, C = Sum x^2*m^4   per region.
// Mask 2x2-upsample factoring: 4 x-elements (2x2 pixel block = elements
// {0,1}/{2,3} of two vertically adjacent rows) share one mask scalar:
//   sx = sum4(x), sq = sum4(x^2);  A += sx*m; B += (sx*m)*m^2; C += sq*m^4.
// grid = 2*NPART*NCH, bid = tensor*2048 + part*512 + ch.
// ---------------------------------------------------------------------------
__global__ __launch_bounds__(256) void k_reduce(const float4* __restrict__ x1,
                                                const float4* __restrict__ x2,
                                                const float* __restrict__ mask) {
    int bid  = blockIdx.x;
    int ch   = bid & (NCH - 1);
    int part = (bid >> 9) & (NPART - 1);
    int tensor = bid >> 11;           // 0 = x1, 1 = x2
    int b  = ch >> 7;
    const float4* p = (tensor ? x2 : x1) + (size_t)ch * (HW / 4) + part * 4096;
    const float*  mb = mask + b * MHW;
    int t = threadIdx.x;
    int lane = t & 31, wid = t >> 5;
    int col = t & 63;                 // float4 column within x row (0..63)
    int rpl0 = t >> 6;                // local row-pair slot (0..3)

    float a0 = 0.f, a1 = 0.f, a2 = 0.f, a3 = 0.f, a4 = 0.f, a5 = 0.f;

#pragma unroll 1
    for (int k = 0; k < 8; k++) {
        int rp = k * 4 + rpl0;        // local row-pair 0..31 within part
        int q0 = rp * 128 + col;      // x row 2*rp
        // front-loaded loads: 2x LDG.128 + 1x LDG.64
        float4 xa = __ldcs(p + q0);
        float4 xb = __ldcs(p + q0 + 64);
        int mrow = part * 32 + rp;
        float2 mp = *reinterpret_cast<const float2*>(mb + mrow * 128 + 2 * col);

#pragma unroll
        for (int hsel = 0; hsel < 2; hsel++) {
            float m = hsel ? mp.y : mp.x;
            float e0 = hsel ? xa.z : xa.x, e1 = hsel ? xa.w : xa.y;
            float e2 = hsel ? xb.z : xb.x, e3 = hsel ? xb.w : xb.y;

            float om = 1.0f - m;
            float m2 = m * m, om2 = om * om;

            float sx = (e0 + e1) + (e2 + e3);
            float sq = fmaf(e0, e0, fmaf(e1, e1, fmaf(e2, e2, e3 * e3)));
            a0 = fmaf(sx, m, a0);
            a1 = fmaf(sx * m, m2, a1);
            a2 = fmaf(sq, m2 * m2, a2);
            a3 = fmaf(sx, om, a3);
            a4 = fmaf(sx * om, om2, a4);
            a5 = fmaf(sq, om2 * om2, a5);
        }
    }

    float vals[6] = {a0, a1, a2, a3, a4, a5};
    __shared__ float red[6][8];
#pragma unroll
    for (int i = 0; i < 6; i++) {
        float s = warpSum(vals[i]);
        if (lane == 0) red[i][wid] = s;
    }
    __syncthreads();
    if (wid == 0) {
#pragma unroll
        for (int i = 0; i < 6; i++) {
            float s = (lane < 8) ? red[i][lane] : 0.f;
            s = warpSum(s);
            if (lane == 0)
                g_sums[(size_t)(part * NCH + ch) * 12 + tensor * 6 + i] = s;
        }
    }
    __threadfence();
    __syncthreads();
    gdc_launch_dependents();
}

// ---------------------------------------------------------------------------
// Kernel 2: stats + modulation GEMVs. grid (BN, 4 row-groups), 16 blocks.
// PRE-WAIT: per-batch mask sums (input-only) overlap with k_reduce's drain.
// POST-WAIT: combine partials, per-channel stats, GEMV (warp-per-row,
// lane along j), coefficients:  out = x1*(m^2*P + om^2*Q) + k1*m + k2*om
// ---------------------------------------------------------------------------
__global__ __launch_bounds__(256) void k_small(const float* __restrict__ mask,
                                               const float* __restrict__ w_in_mean,
                                               const float* __restrict__ w_in_var,
                                               const float* __restrict__ w_out_mean,
                                               const float* __restrict__ w_out_var) {
    int b  = blockIdx.x;
    int cg = blockIdx.y;              // rows [cg*32, cg*32+32)
    int t = threadIdx.x;
    int lane = t & 31, wid = t >> 5;

    __shared__ float sred[2][8];
    __shared__ float ssum[CN * 12];
    __shared__ float v_sh[4 * 256];
    __shared__ float mr_sh[512];      // mu_in, r_in, mu_out, r_out
    __shared__ float ada_sh[128];     // [mat*32 + local_row]
    __shared__ float sh_nin, sh_nout, sh_M2, sh_M2o;

    // ---- pre-wait: mask sums (exact: 2x2-repeat upsample) ----
    const float* mb = mask + b * MHW;
    {
        float s1 = 0, s2 = 0;
        for (int i = t; i < MHW; i += 256) { float m = mb[i]; s1 += m; s2 += m * m; }
        s1 = warpSum(s1); s2 = warpSum(s2);
        if (lane == 0) { sred[0][wid] = s1; sred[1][wid] = s2; }
    }
    __syncthreads();
    if (t == 0) {
        float S1 = 0, S2 = 0;
        for (int i = 0; i < 8; i++) { S1 += sred[0][i]; S2 += sred[1][i]; }
        float msum = 4.f * S1, m2sum = 4.f * S2;
        sh_nin  = msum + EPS;
        sh_nout = ((float)HW - msum) + EPS;
        sh_M2   = m2sum;
        sh_M2o  = (float)HW - 2.f * msum + m2sum;  // Sum (1-m)^2
    }

    // ---- wait for k_reduce's g_sums ----
    gdc_wait();

    for (int id = t; id < CN * 12; id += 256) {
        int c = id / 12, i = id - c * 12;
        float v = 0.f;
#pragma unroll
        for (int p = 0; p < NPART; p++)
            v += g_sums[(size_t)(p * NCH + b * CN + c) * 12 + i];
        ssum[id] = v;
    }
    __syncthreads();

    {
        int c = t & 127;
        int isx2 = t >> 7;
        const float* s = ssum + c * 12 + isx2 * 6;
        float A = s[0], Bb = s[1], Cc = s[2], Ao = s[3], Bo = s[4], Co = s[5];
        float mean_in = A / sh_nin;
        float var_in = (Cc - 2.f * mean_in * Bb + mean_in * mean_in * sh_M2) / sh_nin;
        var_in = fmaxf(var_in, 0.f);
        float mean_out = Ao / sh_nout;
        float var_out = (Co - 2.f * mean_out * Bo + mean_out * mean_out * sh_M2o) / sh_nout;
        var_out = fmaxf(var_out, 0.f);
        int vi = isx2 * 128 + c;
        v_sh[vi]       = mean_in;
        v_sh[256 + vi] = var_in;
        v_sh[512 + vi] = mean_out;
        v_sh[768 + vi] = var_out;
        if (!isx2) {
            mr_sh[c]       = mean_in;
            mr_sh[128 + c] = rsqrtf(var_in + EPS);
            mr_sh[256 + c] = mean_out;
            mr_sh[384 + c] = rsqrtf(var_out + EPS);
        }
    }
    __syncthreads();

    {
        const float* wmats[4] = {w_in_mean, w_in_var, w_out_mean, w_out_var};
#pragma unroll
        for (int it = 0; it < 16; it++) {
            int task = wid * 16 + it;          // 0..127 == mat*32 + lr
            int mat = task >> 5, lr = task & 31;
            const float* wrow = wmats[mat] + (size_t)(cg * 32 + lr) * 256;
            const float* vv = v_sh + mat * 256;
            float a = 0.f;
#pragma unroll
            for (int j = 0; j < 8; j++)
                a = fmaf(__ldg(wrow + lane + 32 * j), vv[lane + 32 * j], a);
            a = warpSum(a);
            if (lane == 0) ada_sh[task] = a;
        }
    }
    __syncthreads();

    if (t < 32) {
        int c = cg * 32 + t;
        float mu_i = mr_sh[c], r_i = mr_sh[128 + c];
        float mu_o = mr_sh[256 + c], r_o = mr_sh[384 + c];
        float P  = r_i * ada_sh[32 + t];          // in_var
        float Q  = r_o * ada_sh[96 + t];          // out_var
        float k1 = ada_sh[t]      - mu_i * P;     // in_mean
        float k2 = ada_sh[64 + t] - mu_o * Q;     // out_mean
        reinterpret_cast<float4*>(g_coef)[b * CN + c] = make_float4(P, Q, k1, k2);
    }
    __threadfence();
    __syncthreads();
    gdc_launch_dependents();
}

// ---------------------------------------------------------------------------
// Kernel 3: elementwise apply (measured 36.4us body). PRE-WAIT: issue
// x1 + mask loads (input-only); POST-WAIT: read g_coef, compute, store.
// out = x1*(m^2*P + om^2*Q) + k1*m + k2*om
// ---------------------------------------------------------------------------
__global__ __launch_bounds__(256) void k_apply(const float4* __restrict__ x1,
                                               const float* __restrict__ mask,
                                               float4* __restrict__ out) {
    int ch = blockIdx.y;
    int b = ch >> 7;
    const float* mb = mask + b * MHW;
    const float4* px = x1 + (size_t)ch * (HW / 4);
    float4* po = out + (size_t)ch * (HW / 4);
    int q0 = blockIdx.x * 512 + threadIdx.x;

    // pre-wait independent loads
    float4 v0 = px[q0];
    float4 v1 = px[q0 + 256];
    int mi0 = ((q0 >> 7) << 7) | ((2 * q0) & 126);
    int q1 = q0 + 256;
    int mi1 = ((q1 >> 7) << 7) | ((2 * q1) & 126);
    float2 mp0 = *reinterpret_cast<const float2*>(mb + mi0);
    float2 mp1 = *reinterpret_cast<const float2*>(mb + mi1);

    gdc_wait();

    float4 coef = __ldg(&reinterpret_cast<const float4*>(g_coef)[ch]);
    float P = coef.x, Q = coef.y, k1 = coef.z, k2 = coef.w;

#pragma unroll
    for (int r = 0; r < 2; r++) {
        int q = r ? q1 : q0;
        float4 v = r ? v1 : v0;
        float2 mp = r ? mp1 : mp0;
        float xs[4] = {v.x, v.y, v.z, v.w};
        float ms[4] = {mp.x, mp.x, mp.y, mp.y};
        float os[4];
#pragma unroll
        for (int i = 0; i < 4; i++) {
            float m = ms[i], om = 1.f - m;
            float s = m * m * P + om * om * Q;
            os[i] = xs[i] * s + k1 * m + k2 * om;
        }
        po[q] = make_float4(os[0], os[1], os[2], os[3]);
    }
}

extern "C" void kernel_launch(void* const* d_in, const int* in_sizes, int n_in,
                              void* d_out, int out_size) {
    const float* x1         = (const float*)d_in[0];
    const float* x2         = (const float*)d_in[1];
    const float* mask       = (const float*)d_in[2];
    const float* w_in_mean  = (const float*)d_in[3];
    const float* w_in_var   = (const float*)d_in[4];
    const float* w_out_mean = (const float*)d_in[5];
    const float* w_out_var  = (const float*)d_in[6];
    float* out = (float*)d_out;

    // 1) reduce — plain launch, tensor-split grid
    k_reduce<<<2 * NPART * NCH, 256>>>((const float4*)x1, (const float4*)x2, mask);

    // 2) stats+gemv — PDL consumer of reduce
    {
        cudaLaunchConfig_t cfg = {};
        cfg.gridDim = dim3(BN, 4);
        cfg.blockDim = dim3(256);
        cudaLaunchAttribute attr[1];
        attr[0].id = cudaLaunchAttributeProgrammaticStreamSerialization;
        attr[0].val.programmaticStreamSerializationAllowed = 1;
        cfg.attrs = attr;
        cfg.numAttrs = 1;
        cudaLaunchKernelEx(&cfg, k_small, mask, w_in_mean, w_in_var, w_out_mean, w_out_var);
    }

    // 3) apply — PDL consumer of k_small
    {
        cudaLaunchConfig_t cfg = {};
        cfg.gridDim = dim3(HW / 4 / 512, NCH);
        cfg.blockDim = dim3(256);
        cudaLaunchAttribute attr[1];
        attr[0].id = cudaLaunchAttributeProgrammaticStreamSerialization;
        attr[0].val.programmaticStreamSerializationAllowed = 1;
        cfg.attrs = attr;
        cfg.numAttrs = 1;
        cudaLaunchKernelEx(&cfg, k_apply, (const float4*)x1, mask, (float4*)out);
    }
}